// round 16
// baseline (speedup 1.0000x reference)
#include <cuda_runtime.h>
#include <cuda_fp16.h>
#include <cstdint>

// ---------------- problem constants ----------------
#define B_ROWS 16384
#define DIN 512
#define DOUT 512
#define NE 8
#define GCOLS 2

// ---------------- GEMM tiling ----------------
#define TM 128
#define TN 128
#define TK 32
#define NSTAGE (DIN / TK)          // 16
#define NCOLT (DOUT / TN)          // 4

#define SA 40      // A16 smem row stride (halves): 80B
#define SB 136     // B smem row stride (halves): 272B

// smem layout (bytes)
#define A32OF 1024
#define A32BUF (TM * TK * 4)            // 16384 (linear, 128B rows), x2
#define A16OF (A32OF + 2 * A32BUF)      // 33792
#define A16BUF (TM * SA * 2)            // 10240, x2
#define B16OF (A16OF + 2 * A16BUF)      // 54272
#define B16BUF (TK * SB * 2)            // 8704, x2
#define GEMM_SMEM (B16OF + 2 * B16BUF)  // 71680 -> 2 CTAs/SM

#define GEMM_GRID 304

// ---------------- device scratch ----------------
__device__ int g_fill[NE];
__device__ int g_work;
__device__ int g_done;
__device__ int g_rowpad[NE * B_ROWS];

__device__ __align__(16) __half g_wh[NE * DIN * DOUT];   // [e][k][n]

// ---------------- helpers ----------------
__device__ __forceinline__ uint32_t smem_u32(const void* p) {
    uint32_t a;
    asm("{ .reg .u64 t; cvta.to.shared.u64 t, %1; cvt.u32.u64 %0, t; }" : "=r"(a) : "l"(p));
    return a;
}
__device__ __forceinline__ void ldsm_x4(uint32_t* r, uint32_t addr) {
    asm volatile("ldmatrix.sync.aligned.m8n8.x4.shared.b16 {%0,%1,%2,%3}, [%4];"
                 : "=r"(r[0]), "=r"(r[1]), "=r"(r[2]), "=r"(r[3]) : "r"(addr));
}
__device__ __forceinline__ void ldsm_x4_t(uint32_t* r, uint32_t addr) {
    asm volatile("ldmatrix.sync.aligned.m8n8.x4.trans.shared.b16 {%0,%1,%2,%3}, [%4];"
                 : "=r"(r[0]), "=r"(r[1]), "=r"(r[2]), "=r"(r[3]) : "r"(addr));
}
__device__ __forceinline__ void mma_f16(float* c, const uint32_t* a, const uint32_t* b) {
    asm volatile(
        "mma.sync.aligned.m16n8k16.row.col.f32.f16.f16.f32 "
        "{%0,%1,%2,%3}, {%4,%5,%6,%7}, {%8,%9}, {%0,%1,%2,%3};"
        : "+f"(c[0]), "+f"(c[1]), "+f"(c[2]), "+f"(c[3])
        : "r"(a[0]), "r"(a[1]), "r"(a[2]), "r"(a[3]), "r"(b[0]), "r"(b[1]));
}
__device__ __forceinline__ void cvt_chunk(uint32_t src, uint32_t dst) {
    float x0, x1, x2, x3;
    asm volatile("ld.shared.v4.f32 {%0,%1,%2,%3}, [%4];"
                 : "=f"(x0), "=f"(x1), "=f"(x2), "=f"(x3) : "r"(src));
    uint32_t h0, h1;
    asm volatile("cvt.rn.f16x2.f32 %0, %1, %2;" : "=r"(h0) : "f"(x1), "f"(x0));
    asm volatile("cvt.rn.f16x2.f32 %0, %1, %2;" : "=r"(h1) : "f"(x3), "f"(x2));
    asm volatile("st.shared.v2.u32 [%0], {%1,%2};" :: "r"(dst), "r"(h0), "r"(h1) : "memory");
}
#define CP_ASYNC16(saddr, gaddr) \
    asm volatile("cp.async.cg.shared.global [%0], [%1], 16;" :: "r"(saddr), "l"(gaddr))
#define CP_COMMIT() asm volatile("cp.async.commit_group;")
#define CP_WAIT0()  asm volatile("cp.async.wait_group 0;" ::: "memory")
#define PAIR_BAR(id) asm volatile("bar.sync %0, 64;" :: "r"(id) : "memory")

// ---------------- prep: cvt W, scatter ----------------
#define WBLOCKS (NE * DIN * DOUT / 4 / 256)
#define SBLOCKS (B_ROWS / 256)
#define PREP_GRID (WBLOCKS + SBLOCKS)

__global__ void prep_kernel(const float* __restrict__ W, const int* __restrict__ groups) {
    int bid = blockIdx.x;
    if (bid < WBLOCKS) {
        int i = bid * blockDim.x + threadIdx.x;
        float4 v = ((const float4*)W)[i];
        __half2 h0 = __floats2half2_rn(v.x, v.y);
        __half2 h1 = __floats2half2_rn(v.z, v.w);
        ((uint2*)g_wh)[i] = make_uint2(*(uint32_t*)&h0, *(uint32_t*)&h1);
    } else {
        int b = (bid - WBLOCKS) * blockDim.x + threadIdx.x;
        int e = groups[b * GCOLS];
        int lane = threadIdx.x & 31;
        unsigned mask = __match_any_sync(0xffffffffu, e);
        int leader = __ffs(mask) - 1;
        int prefix = __popc(mask & ((1u << lane) - 1));
        int base = 0;
        if (lane == leader) base = atomicAdd(&g_fill[e], __popc(mask));
        base = __shfl_sync(0xffffffffu, base, leader);
        g_rowpad[e * B_ROWS + base + prefix] = b;
    }
}

// ---------------- persistent grouped GEMM: pair-local convert ----------------
__global__ __launch_bounds__(256, 2)
void gemm_mma(const float* __restrict__ x, const float* __restrict__ bias,
              float* __restrict__ out) {
    extern __shared__ char sm[];
    int* sm_w   = (int*)sm;
    int* s_cum  = (int*)(sm + 16);
    int* s_fill = (int*)(sm + 64);
    int* srows  = (int*)(sm + 256);
    const uint32_t smu = smem_u32(sm);

    const int tid  = threadIdx.x;
    const int lane = tid & 31;
    const int wid  = tid >> 5;
    const int pg   = wid >> 1;        // M-group / warp-pair id (0..3)
    const int pt   = tid & 63;        // thread within pair

    if (tid < NE) s_fill[tid] = g_fill[tid];
    __syncthreads();
    if (tid == 0) {
        int c = 0;
        s_cum[0] = 0;
        for (int e = 0; e < NE; e++) {
            c += (s_fill[e] + TM - 1) / TM;
            s_cum[e + 1] = c;
        }
    }
    __syncthreads();
    const int nwork = s_cum[NE] * NCOLT;

    const int m0w = pg * 32;
    const int n0w = (wid & 1) * 64;
    const int lr = (lane & 7) + ((lane >> 3) & 1) * 8;
    const int lc = (lane >> 4) * 8;
    const int a_lm_base = ((m0w + lr) * SA + lc) * 2;
    const int b_lm_base = (lr * SB + n0w + lc) * 2;

    // A32 cp.async (CTA-wide): 4 chunks/thread; chunk c: row c>>3, sector c&7
    uint32_t a32s[4];
#pragma unroll
    for (int t = 0; t < 4; t++) {
        int c = tid + t * 256;
        a32s[t] = smu + A32OF + (c >> 3) * 128 + (c & 7) * 16;
    }
    // convert slots (pair-local): 4 chunks/thread over own 32 rows x 8 sectors
    uint32_t cv32[4], cv16[4];
#pragma unroll
    for (int t = 0; t < 4; t++) {
        int j = pt + t * 64;                      // 0..255
        int row = pg * 32 + (j >> 3);
        int sec = j & 7;
        cv32[t] = smu + A32OF + row * 128 + sec * 16;
        cv16[t] = smu + A16OF + row * (SA * 2) + sec * 8;
    }
    // B cp.async: 2 chunks/thread; c: k = c>>4, sector = c&15
    int bk[2];
    uint32_t bso[2];
#pragma unroll
    for (int t = 0; t < 2; t++) {
        int c = tid + t * 256;
        bk[t] = c >> 4;
        bso[t] = smu + B16OF + bk[t] * (SB * 2) + (c & 15) * 16;
    }
    const int bsec = tid & 15;

    const int rl = lane >> 2;
    const int cl = (lane & 3) * 2;

    for (;;) {
        if (tid == 0) sm_w[0] = atomicAdd(&g_work, 1);
        __syncthreads();
        const int w = sm_w[0];
        if (w >= nwork) break;

        const int n0 = (w & (NCOLT - 1)) * TN;
        const int t  = w >> 2;
        int e = 0;
        while (t >= s_cum[e + 1]) e++;
        const int rowbase = (t - s_cum[e]) * TM;
        const int cnt  = s_fill[e];
        const int rows = (cnt - rowbase < TM) ? (cnt - rowbase) : TM;

        if (tid < TM) srows[tid] = (tid < rows) ? g_rowpad[e * B_ROWS + rowbase + tid] : -1;
        __syncthreads();

        const float* agp[4];
#pragma unroll
        for (int tt = 0; tt < 4; tt++) {
            int c = tid + tt * 256;
            int gr = srows[c >> 3]; if (gr < 0) gr = 0;
            agp[tt] = x + (size_t)gr * DIN + (c & 7) * 4;
        }
        const __half* bg[2];
#pragma unroll
        for (int tt = 0; tt < 2; tt++)
            bg[tt] = g_wh + ((size_t)e * DIN + bk[tt]) * DOUT + n0 + bsec * 8;

        float c[2][8][4];
#pragma unroll
        for (int mt = 0; mt < 2; mt++)
#pragma unroll
            for (int nt = 0; nt < 8; nt++)
#pragma unroll
                for (int j = 0; j < 4; j++) c[mt][nt][j] = 0.f;

        // prologue: fill stage 0 into A32[0], B[0]
#pragma unroll
        for (int tt = 0; tt < 4; tt++) CP_ASYNC16(a32s[tt], agp[tt]);
#pragma unroll
        for (int tt = 0; tt < 2; tt++) CP_ASYNC16(bso[tt], bg[tt]);
        CP_COMMIT();

        for (int kt = 0; kt < NSTAGE; kt++) {
            CP_WAIT0();
            __syncthreads();   // stage-kt data arrived; all prior converts/MMAs ordered

            // fill stage kt+1: A32 -> A32[(kt+1)&1], B -> B[(kt+1)&1]
            // (prev contents' readers, convert(kt-1)/MMA(kt-1), precede the sync above)
            if (kt + 1 < NSTAGE) {
                const uint32_t ao = ((kt + 1) & 1) * A32BUF;
                const uint32_t bo = ((kt + 1) & 1) * B16BUF;
                const int ka = (kt + 1) * TK;
                const size_t kb = (size_t)((kt + 1) * TK) * DOUT;
#pragma unroll
                for (int tt = 0; tt < 4; tt++) CP_ASYNC16(a32s[tt] + ao, agp[tt] + ka);
#pragma unroll
                for (int tt = 0; tt < 2; tt++) CP_ASYNC16(bso[tt] + bo, bg[tt] + kb);
            }
            CP_COMMIT();

            // convert(kt): each warp-pair converts ITS OWN 32 A rows -> A16[kt&1]
            {
                const uint32_t off32 = (kt & 1) * A32BUF;
                const uint32_t off16 = (kt & 1) * A16BUF;
#pragma unroll
                for (int tt = 0; tt < 4; tt++) cvt_chunk(cv32[tt] + off32, cv16[tt] + off16);
            }
            PAIR_BAR(1 + pg);   // only the 2 warps of this M-group rendezvous

            // MMA(kt)
            const uint32_t ab = smu + A16OF + (kt & 1) * A16BUF;
            const uint32_t bb = smu + B16OF + (kt & 1) * B16BUF;
#pragma unroll
            for (int ks = 0; ks < 2; ks++) {
                const int kso = ks * 16;
                uint32_t ah[2][4];
#pragma unroll
                for (int mt = 0; mt < 2; mt++)
                    ldsm_x4(ah[mt], ab + a_lm_base + (mt * 16 * SA + kso) * 2);
                uint32_t bh[4][4];
#pragma unroll
                for (int p = 0; p < 4; p++)
                    ldsm_x4_t(bh[p], bb + b_lm_base + (kso * SB + p * 16) * 2);
#pragma unroll
                for (int mt = 0; mt < 2; mt++)
#pragma unroll
                    for (int p = 0; p < 4; p++) {
                        mma_f16(c[mt][2 * p],     ah[mt], &bh[p][0]);
                        mma_f16(c[mt][2 * p + 1], ah[mt], &bh[p][2]);
                    }
            }
        }

        // epilogue
#pragma unroll
        for (int mt = 0; mt < 2; mt++) {
            const int lm0 = m0w + mt * 16 + rl;
            const int r0 = srows[lm0];
            const int r1 = srows[lm0 + 8];
#pragma unroll
            for (int nt = 0; nt < 8; nt++) {
                const int gcol = n0 + n0w + nt * 8 + cl;
                const float2 bv2 = *(const float2*)(bias + e * DOUT + gcol);
                if (r0 >= 0) {
                    float2 v = make_float2(c[mt][nt][0] + bv2.x, c[mt][nt][1] + bv2.y);
                    *(float2*)(out + (size_t)r0 * DOUT + gcol) = v;
                }
                if (r1 >= 0) {
                    float2 v = make_float2(c[mt][nt][2] + bv2.x, c[mt][nt][3] + bv2.y);
                    *(float2*)(out + (size_t)r1 * DOUT + gcol) = v;
                }
            }
        }
        __syncthreads();
    }

    __syncthreads();
    if (tid == 0) {
        int prev = atomicAdd(&g_done, 1);
        if (prev == GEMM_GRID - 1) {
#pragma unroll
            for (int i = 0; i < NE; i++) g_fill[i] = 0;
            g_work = 0;
            g_done = 0;
            __threadfence();
        }
    }
}

// ---------------- launch ----------------
extern "C" void kernel_launch(void* const* d_in, const int* in_sizes, int n_in,
                              void* d_out, int out_size) {
    const float* x      = (const float*)d_in[0];
    const int*   groups = (const int*)d_in[1];
    const float* W      = (const float*)d_in[2];
    const float* bias   = (const float*)d_in[3];
    float*       out    = (float*)d_out;

    cudaFuncSetAttribute(gemm_mma, cudaFuncAttributeMaxDynamicSharedMemorySize, GEMM_SMEM);

    prep_kernel<<<PREP_GRID, 256>>>(W, groups);
    gemm_mma<<<GEMM_GRID, 256, GEMM_SMEM>>>(x, bias, out);
}

// round 17
// speedup vs baseline: 1.0075x; 1.0075x over previous
#include <cuda_runtime.h>
#include <cuda_fp16.h>
#include <cstdint>

// ---------------- problem constants ----------------
#define B_ROWS 16384
#define DIN 512
#define DOUT 512
#define NE 8
#define GCOLS 2

// ---------------- GEMM tiling (R12 config) ----------------
#define TM 128
#define TN 128
#define TK 64
#define NSTAGE (DIN / TK)          // 8
#define NCOLT (DOUT / TN)          // 4

#define SA 72      // A16 smem row stride (halves): 144B = 9 granules (odd -> conflict-free)
#define SB 136     // B smem row stride (halves): 272B

// smem layout (bytes)
#define A32OF 1024                      // fp32 A staging, LINEAR 128 rows x 256B
#define A32BYTES 32768
#define A16OF (A32OF + A32BYTES)        // 33792; two fp16 A buffers
#define A16BUF (TM * SA * 2)            // 18432
#define B16OF (A16OF + 2 * A16BUF)      // 70656; two fp16 B buffers
#define B16BUF (TK * SB * 2)            // 17408
#define GEMM_SMEM (B16OF + 2 * B16BUF)  // 105472 -> 2 CTAs/SM

#define GEMM_GRID 304   // 2 CTAs/SM x 152 SMs, all co-resident

// ---------------- device scratch ----------------
__device__ int g_fill[NE];       // zero at start; self-reset by gemm
__device__ int g_work;
__device__ int g_done;
__device__ int g_rowpad[NE * B_ROWS];

__device__ __align__(16) __half g_wh[NE * DIN * DOUT];   // 4MB, [e][k][n]

// ---------------- helpers ----------------
__device__ __forceinline__ uint32_t smem_u32(const void* p) {
    uint32_t a;
    asm("{ .reg .u64 t; cvta.to.shared.u64 t, %1; cvt.u32.u64 %0, t; }" : "=r"(a) : "l"(p));
    return a;
}
__device__ __forceinline__ void ldsm_x4(uint32_t* r, uint32_t addr) {
    asm volatile("ldmatrix.sync.aligned.m8n8.x4.shared.b16 {%0,%1,%2,%3}, [%4];"
                 : "=r"(r[0]), "=r"(r[1]), "=r"(r[2]), "=r"(r[3]) : "r"(addr));
}
__device__ __forceinline__ void ldsm_x4_t(uint32_t* r, uint32_t addr) {
    asm volatile("ldmatrix.sync.aligned.m8n8.x4.trans.shared.b16 {%0,%1,%2,%3}, [%4];"
                 : "=r"(r[0]), "=r"(r[1]), "=r"(r[2]), "=r"(r[3]) : "r"(addr));
}
__device__ __forceinline__ void mma_f16(float* c, const uint32_t* a, const uint32_t* b) {
    asm volatile(
        "mma.sync.aligned.m16n8k16.row.col.f32.f16.f16.f32 "
        "{%0,%1,%2,%3}, {%4,%5,%6,%7}, {%8,%9}, {%0,%1,%2,%3};"
        : "+f"(c[0]), "+f"(c[1]), "+f"(c[2]), "+f"(c[3])
        : "r"(a[0]), "r"(a[1]), "r"(a[2]), "r"(a[3]), "r"(b[0]), "r"(b[1]));
}
// convert 8 consecutive fp32 (smem) -> 8 fp16, one STS.128
__device__ __forceinline__ void cvt_chunk8(uint32_t src, uint32_t dst) {
    float x0, x1, x2, x3, x4, x5, x6, x7;
    asm volatile("ld.shared.v4.f32 {%0,%1,%2,%3}, [%4];"
                 : "=f"(x0), "=f"(x1), "=f"(x2), "=f"(x3) : "r"(src));
    asm volatile("ld.shared.v4.f32 {%0,%1,%2,%3}, [%4];"
                 : "=f"(x4), "=f"(x5), "=f"(x6), "=f"(x7) : "r"(src + 16));
    uint32_t h0, h1, h2, h3;
    asm volatile("cvt.rn.f16x2.f32 %0, %1, %2;" : "=r"(h0) : "f"(x1), "f"(x0));
    asm volatile("cvt.rn.f16x2.f32 %0, %1, %2;" : "=r"(h1) : "f"(x3), "f"(x2));
    asm volatile("cvt.rn.f16x2.f32 %0, %1, %2;" : "=r"(h2) : "f"(x5), "f"(x4));
    asm volatile("cvt.rn.f16x2.f32 %0, %1, %2;" : "=r"(h3) : "f"(x7), "f"(x6));
    asm volatile("st.shared.v4.b32 [%0], {%1,%2,%3,%4};"
                 :: "r"(dst), "r"(h0), "r"(h1), "r"(h2), "r"(h3) : "memory");
}
#define CP_ASYNC16(saddr, gaddr) \
    asm volatile("cp.async.cg.shared.global [%0], [%1], 16;" :: "r"(saddr), "l"(gaddr))
#define CP_COMMIT() asm volatile("cp.async.commit_group;")
#define CP_WAIT0()  asm volatile("cp.async.wait_group 0;" ::: "memory")

// ---------------- prep: cvt W, scatter ----------------
#define WBLOCKS (NE * DIN * DOUT / 4 / 256)    // 2048
#define SBLOCKS (B_ROWS / 256)                 // 64
#define PREP_GRID (WBLOCKS + SBLOCKS)

__global__ void prep_kernel(const float* __restrict__ W, const int* __restrict__ groups) {
    int bid = blockIdx.x;
    if (bid < WBLOCKS) {
        int i = bid * blockDim.x + threadIdx.x;
        float4 v = ((const float4*)W)[i];
        __half2 h0 = __floats2half2_rn(v.x, v.y);
        __half2 h1 = __floats2half2_rn(v.z, v.w);
        ((uint2*)g_wh)[i] = make_uint2(*(uint32_t*)&h0, *(uint32_t*)&h1);
    } else {
        int b = (bid - WBLOCKS) * blockDim.x + threadIdx.x;
        int e = groups[b * GCOLS];
        int lane = threadIdx.x & 31;
        unsigned mask = __match_any_sync(0xffffffffu, e);
        int leader = __ffs(mask) - 1;
        int prefix = __popc(mask & ((1u << lane) - 1));
        int base = 0;
        if (lane == leader) base = atomicAdd(&g_fill[e], __popc(mask));
        base = __shfl_sync(0xffffffffu, base, leader);
        g_rowpad[e * B_ROWS + base + prefix] = b;
    }
}

// ---------------- persistent grouped GEMM: R12 + STS.128 convert + early B fill ----------------
__global__ __launch_bounds__(256, 2)
void gemm_mma(const float* __restrict__ x, const float* __restrict__ bias,
              float* __restrict__ out) {
    extern __shared__ char sm[];
    int* sm_w   = (int*)sm;
    int* s_cum  = (int*)(sm + 16);
    int* s_fill = (int*)(sm + 64);
    int* srows  = (int*)(sm + 256);
    const uint32_t smu = smem_u32(sm);

    const int tid  = threadIdx.x;
    const int lane = tid & 31;
    const int wid  = tid >> 5;

    if (tid < NE) s_fill[tid] = g_fill[tid];
    __syncthreads();
    if (tid == 0) {
        int c = 0;
        s_cum[0] = 0;
        for (int e = 0; e < NE; e++) {
            c += (s_fill[e] + TM - 1) / TM;
            s_cum[e + 1] = c;
        }
    }
    __syncthreads();
    const int nwork = s_cum[NE] * NCOLT;

    // warp compute coords: warp tile 32x64
    const int m0w = (wid >> 1) * 32;
    const int n0w = (wid & 1) * 64;
    const int lr = (lane & 7) + ((lane >> 3) & 1) * 8;
    const int lc = (lane >> 4) * 8;
    const int a_lm_base = ((m0w + lr) * SA + lc) * 2;
    const int b_lm_base = (lr * SB + n0w + lc) * 2;

    // A32 cp.async: 8 x 16B chunks/thread/stage, LINEAR (row = c>>4, 16 sectors/row)
    const int asec4 = (tid & 15) * 4;
    const uint32_t a32base = smu + A32OF + tid * 16;
    // convert mapping: thread handles rows (tid>>3)+32t, 8 consecutive floats at (tid&7)*8
    const uint32_t cvsrc = smu + A32OF + (tid >> 3) * 256 + (tid & 7) * 32;
    const uint32_t cvdst0 = (tid >> 3) * (SA * 2) + (tid & 7) * 16;

    // B fp16 cp.async: 4 chunks/thread/stage
    int bk[4];
    uint32_t bso[4];
#pragma unroll
    for (int t = 0; t < 4; t++) {
        int c = tid + t * 256;
        bk[t] = c >> 4;
        bso[t] = smu + B16OF + bk[t] * (SB * 2) + (c & 15) * 16;
    }
    const int bsec = tid & 15;

    const int rl = lane >> 2;
    const int cl = (lane & 3) * 2;

    for (;;) {
        if (tid == 0) sm_w[0] = atomicAdd(&g_work, 1);
        __syncthreads();
        const int w = sm_w[0];
        if (w >= nwork) break;

        const int n0 = (w & (NCOLT - 1)) * TN;
        const int t  = w >> 2;
        int e = 0;
        while (t >= s_cum[e + 1]) e++;
        const int rowbase = (t - s_cum[e]) * TM;
        const int cnt  = s_fill[e];
        const int rows = (cnt - rowbase < TM) ? (cnt - rowbase) : TM;

        if (tid < TM) srows[tid] = (tid < rows) ? g_rowpad[e * B_ROWS + rowbase + tid] : -1;
        __syncthreads();

        const float* agp[8];
#pragma unroll
        for (int tt = 0; tt < 8; tt++) {
            int c = tid + tt * 256;
            int gr = srows[c >> 4]; if (gr < 0) gr = 0;
            agp[tt] = x + (size_t)gr * DIN + (c & 15) * 4;
        }
        const __half* bg[4];
#pragma unroll
        for (int tt = 0; tt < 4; tt++)
            bg[tt] = g_wh + ((size_t)e * DIN + bk[tt]) * DOUT + n0 + bsec * 8;

        float c[2][8][4];
#pragma unroll
        for (int mt = 0; mt < 2; mt++)
#pragma unroll
            for (int nt = 0; nt < 8; nt++)
#pragma unroll
                for (int j = 0; j < 4; j++) c[mt][nt][j] = 0.f;

        // prologue: fill stage 0 (A32 + B buf0)
#pragma unroll
        for (int tt = 0; tt < 8; tt++) CP_ASYNC16(a32base + tt * 4096, agp[tt]);
#pragma unroll
        for (int tt = 0; tt < 4; tt++) CP_ASYNC16(bso[tt], bg[tt]);
        CP_COMMIT();

        for (int kt = 0; kt < NSTAGE; kt++) {
            CP_WAIT0();
            __syncthreads();          // A32(kt), B[kt&1] ready

            // early B fill for stage kt+1 (B[(kt+1)&1]'s last readers pre-date the sync)
            if (kt + 1 < NSTAGE) {
                const uint32_t bbo = ((kt + 1) & 1) * B16BUF;
                const size_t kb = (size_t)((kt + 1) * TK) * DOUT;
#pragma unroll
                for (int tt = 0; tt < 4; tt++) CP_ASYNC16(bso[tt] + bbo, bg[tt] + kb);
            }

            // convert A32 (fp32 linear) -> A16[kt&1]: 2xLDS.128 + 4 cvt + 1 STS.128 per t
            const uint32_t a16b = smu + A16OF + (kt & 1) * A16BUF;
#pragma unroll
            for (int k = 0; k < 4; k++)
                cvt_chunk8(cvsrc + k * 8192, a16b + cvdst0 + k * (32 * SA * 2));
            __syncthreads();          // A16 ready; A32 free for refill

            // A32 fill for stage kt+1 (A32 single buffer, safe only after the sync)
            if (kt + 1 < NSTAGE) {
                const int ka = (kt + 1) * TK;
#pragma unroll
                for (int tt = 0; tt < 8; tt++) CP_ASYNC16(a32base + tt * 4096, agp[tt] + ka);
            }
            CP_COMMIT();

            // MMA on A16[kt&1], B[kt&1]
            const uint32_t ab = a16b;
            const uint32_t bb = smu + B16OF + (kt & 1) * B16BUF;
#pragma unroll
            for (int ks = 0; ks < 4; ks++) {
                const int kso = ks * 16;
                uint32_t ah[2][4];
#pragma unroll
                for (int mt = 0; mt < 2; mt++)
                    ldsm_x4(ah[mt], ab + a_lm_base + (mt * 16 * SA + kso) * 2);
                uint32_t bh[4][4];
#pragma unroll
                for (int p = 0; p < 4; p++)
                    ldsm_x4_t(bh[p], bb + b_lm_base + (kso * SB + p * 16) * 2);
#pragma unroll
                for (int mt = 0; mt < 2; mt++)
#pragma unroll
                    for (int p = 0; p < 4; p++) {
                        mma_f16(c[mt][2 * p],     ah[mt], &bh[p][0]);
                        mma_f16(c[mt][2 * p + 1], ah[mt], &bh[p][2]);
                    }
            }
        }

        // epilogue: bias + scattered stores
#pragma unroll
        for (int mt = 0; mt < 2; mt++) {
            const int lm0 = m0w + mt * 16 + rl;
            const int r0 = srows[lm0];
            const int r1 = srows[lm0 + 8];
#pragma unroll
            for (int nt = 0; nt < 8; nt++) {
                const int gcol = n0 + n0w + nt * 8 + cl;
                const float2 bv2 = *(const float2*)(bias + e * DOUT + gcol);
                if (r0 >= 0) {
                    float2 v = make_float2(c[mt][nt][0] + bv2.x, c[mt][nt][1] + bv2.y);
                    *(float2*)(out + (size_t)r0 * DOUT + gcol) = v;
                }
                if (r1 >= 0) {
                    float2 v = make_float2(c[mt][nt][2] + bv2.x, c[mt][nt][3] + bv2.y);
                    *(float2*)(out + (size_t)r1 * DOUT + gcol) = v;
                }
            }
        }
        __syncthreads();
    }

    // self-reset for next replay
    __syncthreads();
    if (tid == 0) {
        int prev = atomicAdd(&g_done, 1);
        if (prev == GEMM_GRID - 1) {
#pragma unroll
            for (int i = 0; i < NE; i++) g_fill[i] = 0;
            g_work = 0;
            g_done = 0;
            __threadfence();
        }
    }
}

// ---------------- launch ----------------
extern "C" void kernel_launch(void* const* d_in, const int* in_sizes, int n_in,
                              void* d_out, int out_size) {
    const float* x      = (const float*)d_in[0];
    const int*   groups = (const int*)d_in[1];
    const float* W      = (const float*)d_in[2];
    const float* bias   = (const float*)d_in[3];
    float*       out    = (float*)d_out;

    cudaFuncSetAttribute(gemm_mma, cudaFuncAttributeMaxDynamicSharedMemorySize, GEMM_SMEM);

    prep_kernel<<<PREP_GRID, 256>>>(W, groups);
    gemm_mma<<<GEMM_GRID, 256, GEMM_SMEM>>>(x, bias, out);
}